// round 3
// baseline (speedup 1.0000x reference)
#include <cuda_runtime.h>

#define N 256
#define BIG 1e9f

// Monotone float -> uint mapping (order-preserving), and exact inverse.
__device__ __forceinline__ unsigned fkey(float f) {
    unsigned b = __float_as_uint(f);
    return ((int)b < 0) ? ~b : (b | 0x80000000u);
}
__device__ __forceinline__ float unfkey(unsigned k) {
    unsigned b = ((int)k < 0) ? (k & 0x7FFFFFFFu) : ~k;
    return __uint_as_float(b);
}

// Single-warp Jonker-Volgenant LAP, absolute-distance Dijkstra form
// (validated bit-exact vs reference in R2: same fp expression order for cur).
//
// Strided column ownership: lane owns (1-indexed) columns lane+1+32*k,
// k=0..7. Consequences:
//  - way[] STS and candidate p[] LDS are bank-conflict-free
//  - row loads are 8 coalesced LDG.32 per lane
//  - warp-argmin ties break by lowest lane = lowest (j-1)%32; exact float
//    ties cannot occur after the first scan step (continuous data), so this
//    matches jnp.argmin's first-index semantics in practice.
//
// dist[k] of a settled (used) column is frozen at its settle-time Dsum, so
// the end-of-row dual update is amt = Dfinal - dist[k] (no mark[] needed).
__global__ __launch_bounds__(32, 1)
void lap_jv_warp3(const float* __restrict__ C, float* __restrict__ out) {
    __shared__ float u0[N + 1];
    __shared__ int   p[N + 1];      // p[j] = row matched to column j (0 = free)
    __shared__ int   way[N + 1];

    const int lane = threadIdx.x;

    for (int k = lane; k <= N; k += 32) { u0[k] = 0.0f; p[k] = 0; }
    float v[8], dist[8];
    #pragma unroll
    for (int k = 0; k < 8; ++k) v[k] = 0.0f;
    __syncwarp();

    for (int i = 1; i <= N; ++i) {
        #pragma unroll
        for (int k = 0; k < 8; ++k) dist[k] = BIG;
        unsigned usedmask = 0;
        float Dsum = 0.0f;
        int j0 = 0, i0 = i, jfree;
        if (lane == 0) p[0] = i;

        for (;;) {
            // ---- loads first: row i0 (coalesced) + u0[i0]; shadow work follows
            const float* rowp = C + (i0 - 1) * N + lane;
            float cc[8];
            #pragma unroll
            for (int k = 0; k < 8; ++k) cc[k] = __ldg(rowp + 32 * k);
            const float ui = u0[i0];

            // shadow: mark column j0 as used (j0 -> lane (j0-1)%32, slot (j0-1)/32)
            {
                const int jz = j0 - 1;                  // -1 for dummy col 0
                if ((jz & 31) == lane && jz >= 0) usedmask |= 1u << (jz >> 5);
            }

            // ---- scan: same fp expression order as the validated R2 kernel
            #pragma unroll
            for (int k = 0; k < 8; ++k) {
                const float cur = cc[k] - ui - v[k] + Dsum;
                if (!((usedmask >> k) & 1u) && cur < dist[k]) {
                    dist[k] = cur;
                    way[lane + 1 + 32 * k] = j0;
                }
            }

            // ---- local argmin: value tree (fminf), masked by usedmask
            float av[8];
            #pragma unroll
            for (int k = 0; k < 8; ++k)
                av[k] = ((usedmask >> k) & 1u) ? __int_as_float(0x7F800000) : dist[k];
            const float m0 = fminf(av[0], av[1]), m1 = fminf(av[2], av[3]);
            const float m2 = fminf(av[4], av[5]), m3 = fminf(av[6], av[7]);
            const float m4 = fminf(m0, m1),       m5 = fminf(m2, m3);
            const float bv = fminf(m4, m5);

            // warp-wide min key (long latency; index search overlaps it)
            const unsigned key  = fkey(bv);
            const unsigned kmin = __reduce_min_sync(0xFFFFFFFFu, key);

            // local index of bv, first-slot-wins (descending select chain)
            int bk = 7;
            #pragma unroll
            for (int k = 6; k >= 0; --k) bk = (av[k] == bv) ? k : bk;
            const int jc = lane + 1 + 32 * bk;
            const int ic = p[jc];                        // LDS hidden under ballot

            const unsigned ball = __ballot_sync(0xFFFFFFFFu, key == kmin);
            const int wl = __ffs(ball) - 1;
            Dsum = unfkey(kmin);                         // winner's value, bit-exact
            j0 = __shfl_sync(0xFFFFFFFFu, jc, wl);
            i0 = __shfl_sync(0xFFFFFFFFu, ic, wl);
            if (i0 == 0) { jfree = j0; break; }
        }

        // ---- end-of-row dual updates; settled dist[k] == its settle-time Dsum
        const float Dfinal = Dsum;
        #pragma unroll
        for (int k = 0; k < 8; ++k) {
            if ((usedmask >> k) & 1u) {
                const float amt = Dfinal - dist[k];
                v[k] -= amt;
                u0[p[lane + 1 + 32 * k]] += amt;         // distinct rows: no conflict
            }
        }
        if (lane == 0) u0[i] += Dfinal;                  // dummy column 0 (p[0]=i)
        __syncwarp();

        if (lane == 0) {                                 // augment path
            int jj = jfree;
            while (jj != 0) { const int j1 = way[jj]; p[jj] = p[j1]; jj = j1; }
        }
        __syncwarp();
    }

    // ---- emit 0/1 labelling
    const float4 z = make_float4(0.f, 0.f, 0.f, 0.f);
    for (int idx = lane; idx < N * N / 4; idx += 32) ((float4*)out)[idx] = z;
    __syncwarp();
    #pragma unroll
    for (int k = 0; k < 8; ++k) {
        const int col = lane + 32 * k;                   // 0-based column
        const int r   = p[col + 1] - 1;                  // 0-based matched row
        out[r * N + col] = 1.0f;
    }
}

extern "C" void kernel_launch(void* const* d_in, const int* in_sizes, int n_in,
                              void* d_out, int out_size) {
    (void)in_sizes; (void)n_in; (void)out_size;
    lap_jv_warp3<<<1, 32>>>((const float*)d_in[0], (float*)d_out);
}

// round 4
// speedup vs baseline: 1.1760x; 1.1760x over previous
#include <cuda_runtime.h>

#define N 256
#define BIG 1e9f

// Monotone float -> uint mapping (order-preserving), and exact inverse.
__device__ __forceinline__ unsigned fkey(float f) {
    unsigned b = __float_as_uint(f);
    return ((int)b < 0) ? ~b : (b | 0x80000000u);
}
__device__ __forceinline__ float unfkey(unsigned k) {
    unsigned b = ((int)k < 0) ? (k & 0x7FFFFFFFu) : ~k;
    return __uint_as_float(b);
}

// Jonker-Volgenant LAP with column-reduction + greedy init, then the
// validated single-warp absolute-distance Dijkstra augmentation for the
// remaining free rows. The optimum for continuous random costs is unique,
// so any exact solver reproduces the reference labelling (empirically
// confirmed: R2/R3 deviated in path order yet matched bit-for-bit).
//
// Phase 1 (256 threads): v[j] = min_i C[i][j], argmin row per column.
//   Fully coalesced read of all of C; also warms L1/L2 for phase 3.
// Phase 2 (thread 0):    greedy assignment from column argmins.
// Phase 3 (warp 0):      Dijkstra augmentation per remaining free row.
//   Invariants: reduced costs >= 0, matched pairs tight; a free row has
//   u0 = 0 at its own turn (dual updates only touch matched rows and the
//   currently-augmenting free row).
__global__ __launch_bounds__(256, 1)
void lap_jv4(const float* __restrict__ C, float* __restrict__ out) {
    __shared__ float u0[N + 1];
    __shared__ float vsh[N + 1];
    __shared__ int   p[N + 1];      // col -> row (0 = free)
    __shared__ int   way[N + 1];
    __shared__ int   rmin[N + 1];   // col -> argmin row
    __shared__ int   xrow[N + 1];   // row -> col (0 = free)
    __shared__ int   freelist[N];
    __shared__ int   nfree;

    const int tid = threadIdx.x;

    // ---- phase 1: column reduction (coalesced across threads for each i)
    {
        float best = C[tid];
        int   bi   = 0;
        #pragma unroll 8
        for (int i = 1; i < N; ++i) {
            const float c = C[i * N + tid];
            if (c < best) { best = c; bi = i; }
        }
        vsh[tid + 1]  = best;
        rmin[tid + 1] = bi + 1;
        u0[tid + 1]   = 0.0f;
        p[tid + 1]    = 0;
        xrow[tid + 1] = 0;
        if (tid == 0) { u0[0] = 0.0f; vsh[0] = 0.0f; p[0] = 0; xrow[0] = 0; }
    }
    __syncthreads();

    // ---- phase 2: greedy assignment (serial, short)
    if (tid == 0) {
        for (int j = 1; j <= N; ++j) {
            const int r = rmin[j];
            if (xrow[r] == 0) { xrow[r] = j; p[j] = r; }
        }
        int nf = 0;
        for (int r = 1; r <= N; ++r) if (xrow[r] == 0) freelist[nf++] = r;
        nfree = nf;
    }
    __syncthreads();

    // ---- phase 3: single-warp augmentation for free rows
    if (tid < 32) {
        const int lane = tid;
        float v[8], dist[8];
        #pragma unroll
        for (int k = 0; k < 8; ++k) v[k] = vsh[lane + 1 + 32 * k];

        const int nf = nfree;
        for (int fr = 0; fr < nf; ++fr) {
            const int i = freelist[fr];
            #pragma unroll
            for (int k = 0; k < 8; ++k) dist[k] = BIG;
            unsigned usedmask = 0;
            float Dsum = 0.0f;
            int j0 = 0, i0 = i, jfree;
            if (lane == 0) p[0] = i;

            for (;;) {
                // loads first; bookkeeping in their shadow
                const float* rowp = C + (i0 - 1) * N + lane;
                float cc[8];
                #pragma unroll
                for (int k = 0; k < 8; ++k) cc[k] = __ldg(rowp + 32 * k);
                const float ui = u0[i0];
                {
                    const int jz = j0 - 1;
                    if ((jz & 31) == lane && jz >= 0) usedmask |= 1u << (jz >> 5);
                }

                #pragma unroll
                for (int k = 0; k < 8; ++k) {
                    const float cur = cc[k] - ui - v[k] + Dsum;
                    if (!((usedmask >> k) & 1u) && cur < dist[k]) {
                        dist[k] = cur;
                        way[lane + 1 + 32 * k] = j0;
                    }
                }

                float av[8];
                #pragma unroll
                for (int k = 0; k < 8; ++k)
                    av[k] = ((usedmask >> k) & 1u) ? __int_as_float(0x7F800000)
                                                   : dist[k];
                const float m0 = fminf(av[0], av[1]), m1 = fminf(av[2], av[3]);
                const float m2 = fminf(av[4], av[5]), m3 = fminf(av[6], av[7]);
                const float bv = fminf(fminf(m0, m1), fminf(m2, m3));

                const unsigned key  = fkey(bv);
                const unsigned kmin = __reduce_min_sync(0xFFFFFFFFu, key);

                int bk = 7;
                #pragma unroll
                for (int k = 6; k >= 0; --k) bk = (av[k] == bv) ? k : bk;
                const int jc = lane + 1 + 32 * bk;
                const int ic = p[jc];                 // hidden under ballot

                const unsigned ball = __ballot_sync(0xFFFFFFFFu, key == kmin);
                const int wl = __ffs(ball) - 1;
                Dsum = unfkey(kmin);
                j0 = __shfl_sync(0xFFFFFFFFu, jc, wl);
                i0 = __shfl_sync(0xFFFFFFFFu, ic, wl);
                if (i0 == 0) { jfree = j0; break; }
            }

            // end-of-row dual updates: settled dist[k] == settle-time Dsum
            const float Dfinal = Dsum;
            #pragma unroll
            for (int k = 0; k < 8; ++k) {
                if ((usedmask >> k) & 1u) {
                    const float amt = Dfinal - dist[k];
                    v[k] -= amt;
                    u0[p[lane + 1 + 32 * k]] += amt;  // distinct rows: safe
                }
            }
            if (lane == 0) u0[i] += Dfinal;           // free row: u0 was 0
            __syncwarp();

            if (lane == 0) {                          // augment path
                int jj = jfree;
                while (jj != 0) { const int j1 = way[jj]; p[jj] = p[j1]; jj = j1; }
            }
            __syncwarp();
        }
    }
    __syncthreads();

    // ---- output: 0/1 labelling
    {
        const float4 z = make_float4(0.f, 0.f, 0.f, 0.f);
        for (int idx = tid; idx < N * N / 4; idx += 256) ((float4*)out)[idx] = z;
    }
    __syncthreads();
    {
        const int col = tid;                          // 0-based column
        const int r   = p[col + 1] - 1;               // 0-based matched row
        out[r * N + col] = 1.0f;
    }
}

extern "C" void kernel_launch(void* const* d_in, const int* in_sizes, int n_in,
                              void* d_out, int out_size) {
    (void)in_sizes; (void)n_in; (void)out_size;
    lap_jv4<<<1, 256>>>((const float*)d_in[0], (float*)d_out);
}